// round 5
// baseline (speedup 1.0000x reference)
#include <cuda_runtime.h>
#include <cstdint>

#define B_  4
#define S_  4096
#define DM  768
#define DK  64
#define NS  4          // KV splits per q-tile

// Scratch (device globals: no allocation allowed)
__device__ float  g_Q [B_ * S_ * DK];   // [b*S+s][d]  (pre-scaled by 1/8)
__device__ float  g_Kt[B_ * DK * S_];   // [b][d][s]   (K transposed)
__device__ float  g_V [B_ * S_ * DK];   // [b*S+s][d]
__device__ float  g_Opart[B_ * NS * 128 * 32 * DK];  // unnormalized partial O
__device__ float2 g_ml   [B_ * NS * 128 * 32];       // per-row (m, l) per split

// ---------------- packed f32x2 helpers (FFMA2 path, sm_100+) ----------------
__device__ __forceinline__ void fma2(uint64_t& acc, uint64_t a, uint64_t b) {
    asm("fma.rn.f32x2 %0, %1, %2, %0;" : "+l"(acc) : "l"(a), "l"(b));
}
__device__ __forceinline__ void mul2(uint64_t& acc, uint64_t a) {
    asm("mul.rn.f32x2 %0, %0, %1;" : "+l"(acc) : "l"(a));
}
__device__ __forceinline__ uint64_t f2u(float x, float y) {
    uint64_t v; asm("mov.b64 %0, {%1,%2};" : "=l"(v) : "f"(x), "f"(y)); return v;
}
__device__ __forceinline__ float2 u2f(uint64_t v) {
    float2 f; asm("mov.b64 {%0,%1}, %2;" : "=f"(f.x), "=f"(f.y) : "l"(v)); return f;
}

// =====================================================================
// Kernel 1: fused QKV projection. grid = 256, block = 256.
// One block computes a 64-row stripe of Q, K, V together (x read ONCE).
// K is written TRANSPOSED to g_Kt[b][d][s]; Q is pre-scaled by 0.125.
// =====================================================================
#define XS_STRIDE 20    // floats per x row (16 + 4 pad)
#define WS_STRIDE 208   // floats per kk row (3*68 + 4 pad)

__global__ __launch_bounds__(256) void proj_kernel(
    const float* __restrict__ x,
    const float* __restrict__ WQ,
    const float* __restrict__ WK,
    const float* __restrict__ WV)
{
    __shared__ float xs[64 * XS_STRIDE];   // [r][kk]
    __shared__ float ws[16 * WS_STRIDE];   // [kk][w*68 + n]

    const int tid = threadIdx.x;
    const int ty = tid >> 4;        // 0..15 -> rows ty*4..+3
    const int tx = tid & 15;        // 0..15 -> cols tx*4..+3
    const int row0 = blockIdx.x * 64;

    const float* __restrict__ Wp0 = WQ;
    const float* __restrict__ Wp1 = WK;
    const float* __restrict__ Wp2 = WV;

    const int xr_r = tid >> 2, xr_c = tid & 3;        // x: 64 rows x 4 float4
    const int w_kk = tid >> 4, w_n4 = tid & 15;       // W: 16 kk x 16 float4 (per W)

    float4 xr = *reinterpret_cast<const float4*>(&x[(row0 + xr_r) * DM + xr_c * 4]);
    float4 wr0 = *reinterpret_cast<const float4*>(&Wp0[w_kk * DK + w_n4 * 4]);
    float4 wr1 = *reinterpret_cast<const float4*>(&Wp1[w_kk * DK + w_n4 * 4]);
    float4 wr2 = *reinterpret_cast<const float4*>(&Wp2[w_kk * DK + w_n4 * 4]);

    uint64_t acc[3][4][2];
#pragma unroll
    for (int w = 0; w < 3; w++)
#pragma unroll
        for (int i = 0; i < 4; i++) { acc[w][i][0] = 0ull; acc[w][i][1] = 0ull; }

    for (int k0 = 0; k0 < DM; k0 += 16) {
        __syncthreads();
        *reinterpret_cast<float4*>(&xs[xr_r * XS_STRIDE + xr_c * 4]) = xr;
        *reinterpret_cast<float4*>(&ws[w_kk * WS_STRIDE + 0 * 68 + w_n4 * 4]) = wr0;
        *reinterpret_cast<float4*>(&ws[w_kk * WS_STRIDE + 1 * 68 + w_n4 * 4]) = wr1;
        *reinterpret_cast<float4*>(&ws[w_kk * WS_STRIDE + 2 * 68 + w_n4 * 4]) = wr2;
        __syncthreads();

        if (k0 + 16 < DM) {
            xr  = *reinterpret_cast<const float4*>(&x[(row0 + xr_r) * DM + k0 + 16 + xr_c * 4]);
            wr0 = *reinterpret_cast<const float4*>(&Wp0[(k0 + 16 + w_kk) * DK + w_n4 * 4]);
            wr1 = *reinterpret_cast<const float4*>(&Wp1[(k0 + 16 + w_kk) * DK + w_n4 * 4]);
            wr2 = *reinterpret_cast<const float4*>(&Wp2[(k0 + 16 + w_kk) * DK + w_n4 * 4]);
        }

#pragma unroll
        for (int kg = 0; kg < 4; kg++) {
            float4 av[4];
#pragma unroll
            for (int i = 0; i < 4; i++)
                av[i] = *reinterpret_cast<const float4*>(&xs[(ty * 4 + i) * XS_STRIDE + kg * 4]);
#pragma unroll
            for (int sub = 0; sub < 4; sub++) {
                const int kk = kg * 4 + sub;
                ulonglong2 b0 = *reinterpret_cast<const ulonglong2*>(&ws[kk * WS_STRIDE + 0 * 68 + tx * 4]);
                ulonglong2 b1 = *reinterpret_cast<const ulonglong2*>(&ws[kk * WS_STRIDE + 1 * 68 + tx * 4]);
                ulonglong2 b2 = *reinterpret_cast<const ulonglong2*>(&ws[kk * WS_STRIDE + 2 * 68 + tx * 4]);
#pragma unroll
                for (int i = 0; i < 4; i++) {
                    float q = (&av[i].x)[sub];
                    uint64_t a = f2u(q, q);
                    fma2(acc[0][i][0], a, b0.x); fma2(acc[0][i][1], a, b0.y);
                    fma2(acc[1][i][0], a, b1.x); fma2(acc[1][i][1], a, b1.y);
                    fma2(acc[2][i][0], a, b2.x); fma2(acc[2][i][1], a, b2.y);
                }
            }
        }
    }

    // Epilogue
    const int b  = row0 >> 12;
    const int s0 = row0 & (S_ - 1);
    float kv[4][4];
#pragma unroll
    for (int i = 0; i < 4; i++) {
        const int r = row0 + ty * 4 + i;
        float2 qa = u2f(acc[0][i][0]), qb = u2f(acc[0][i][1]);
        float4 qo = make_float4(qa.x * 0.125f, qa.y * 0.125f, qb.x * 0.125f, qb.y * 0.125f);
        *reinterpret_cast<float4*>(&g_Q[r * DK + tx * 4]) = qo;
        float2 va = u2f(acc[2][i][0]), vb = u2f(acc[2][i][1]);
        *reinterpret_cast<float4*>(&g_V[r * DK + tx * 4]) = make_float4(va.x, va.y, vb.x, vb.y);
        float2 ka = u2f(acc[1][i][0]), kb = u2f(acc[1][i][1]);
        kv[i][0] = ka.x; kv[i][1] = ka.y; kv[i][2] = kb.x; kv[i][3] = kb.y;
    }
#pragma unroll
    for (int c = 0; c < 4; c++) {
        float4 kc = make_float4(kv[0][c], kv[1][c], kv[2][c], kv[3][c]);
        *reinterpret_cast<float4*>(&g_Kt[(b * DK + tx * 4 + c) * S_ + s0 + ty * 4]) = kc;
    }
}

// =====================================================================
// Kernel 2: split-KV causal flash attention, CONTRACTION-PAIR scheme.
// grid = (128, 4, NS), block = 128. Zero splat movs: FMA2 lanes carry
// two consecutive contraction indices; u64 accumulator per output,
// halves summed at the end. K/V tiles stored pair-interleaved in SMEM.
// =====================================================================
#define TSF 68                         // qs/ps float stride
#define KS2 66                         // ks2/vs2 u64 stride
#define OFF_QS 0                       // qs float[32][TSF]  (8704 B)
#define OFF_PS 8704                    // ps float[32][TSF]  (8704 B)
#define OFF_K2 17408                   // ks2 u64[32][KS2]   (16896 B)
#define OFF_V2 34304                   // vs2 u64[32][KS2]   (16896 B)
#define SMEM_TOTAL 51200

__global__ __launch_bounds__(128, 4) void attn_kernel()
{
    extern __shared__ char smraw[];
    float*    qs  = reinterpret_cast<float*>(smraw + OFF_QS);
    float*    ps  = reinterpret_cast<float*>(smraw + OFF_PS);
    uint64_t* ks2 = reinterpret_cast<uint64_t*>(smraw + OFF_K2);
    uint64_t* vs2 = reinterpret_cast<uint64_t*>(smraw + OFF_V2);

    const int tid = threadIdx.x;
    const int ty = tid >> 4;   // 0..7  -> rows ty*4..+3
    const int tx = tid & 15;   // 0..15 -> cols tx*4..+3
    const int b = blockIdx.y;
    const int j = blockIdx.x;
    const int split = blockIdx.z;
    const int q0 = j * 32;
    const int nkv = (j >> 1) + 1;
    const int per = (nkv + NS - 1) / NS;
    const int t0 = split * per;
    const int t1 = min(nkv, t0 + per);
    if (t0 >= t1) return;   // empty split (uniform across block)

    const float* __restrict__ Qb  = g_Q  + b * (S_ * DK);
    const float* __restrict__ Ktb = g_Kt + b * (DK * S_);
    const float* __restrict__ Vb  = g_V  + b * (S_ * DK);

    // Load Q tile (32 x 64) row-major, already scaled
#pragma unroll
    for (int i = 0; i < 4; i++) {
        int lin = tid + i * 128;
        int d4 = lin & 15, r = lin >> 4;
        *reinterpret_cast<float4*>(&qs[r * TSF + d4 * 4]) =
            *reinterpret_cast<const float4*>(&Qb[(q0 + r) * DK + d4 * 4]);
    }

    uint64_t o2[4][4];
    float m[4], l[4];
#pragma unroll
    for (int i = 0; i < 4; i++) {
#pragma unroll
        for (int c = 0; c < 4; c++) o2[i][c] = 0ull;
        m[i] = -1e30f; l[i] = 0.0f;
    }

    for (int t = t0; t < t1; t++) {
        const int k0 = t * 64;
        __syncthreads();   // tiles free for reuse (also covers qs on first iter)

        // K tile: pair-interleave rows (2dp, 2dp+1) of g_Kt -> ks2[dp][key]
        // V tile: pair-interleave rows (2sp, 2sp+1) of V    -> vs2[sp][d]
#pragma unroll
        for (int i = 0; i < 4; i++) {
            int tt = tid + i * 128;
            int rp = tt >> 4, cg = tt & 15;   // rp: d-pair / s-pair; cg: col group
            {
                const float* kp = &Ktb[(2 * rp) * S_ + k0 + cg * 4];
                float4 a = *reinterpret_cast<const float4*>(kp);
                float4 bb = *reinterpret_cast<const float4*>(kp + S_);
                ulonglong2 p01; p01.x = f2u(a.x, bb.x); p01.y = f2u(a.y, bb.y);
                ulonglong2 p23; p23.x = f2u(a.z, bb.z); p23.y = f2u(a.w, bb.w);
                *reinterpret_cast<ulonglong2*>(&ks2[rp * KS2 + cg * 4]) = p01;
                *reinterpret_cast<ulonglong2*>(&ks2[rp * KS2 + cg * 4 + 2]) = p23;
            }
            {
                const float* vp = &Vb[(k0 + 2 * rp) * DK + cg * 4];
                float4 a = *reinterpret_cast<const float4*>(vp);
                float4 bb = *reinterpret_cast<const float4*>(vp + DK);
                ulonglong2 p01; p01.x = f2u(a.x, bb.x); p01.y = f2u(a.y, bb.y);
                ulonglong2 p23; p23.x = f2u(a.z, bb.z); p23.y = f2u(a.w, bb.w);
                *reinterpret_cast<ulonglong2*>(&vs2[rp * KS2 + cg * 4]) = p01;
                *reinterpret_cast<ulonglong2*>(&vs2[rp * KS2 + cg * 4 + 2]) = p23;
            }
        }
        __syncthreads();

        // GEMM1: S = Q @ K^T, contraction over d in pairs. No splats.
        uint64_t s2[4][4];
#pragma unroll
        for (int i = 0; i < 4; i++)
#pragma unroll
            for (int c = 0; c < 4; c++) s2[i][c] = 0ull;

#pragma unroll
        for (int pg = 0; pg < 16; pg++) {          // groups of 2 d-pairs (4 d)
            ulonglong2 qp[4];
#pragma unroll
            for (int i = 0; i < 4; i++)
                qp[i] = *reinterpret_cast<const ulonglong2*>(&qs[(ty * 4 + i) * TSF + pg * 4]);
#pragma unroll
            for (int sp = 0; sp < 2; sp++) {
                const int p = pg * 2 + sp;
                ulonglong2 k01 = *reinterpret_cast<const ulonglong2*>(&ks2[p * KS2 + tx * 4]);
                ulonglong2 k23 = *reinterpret_cast<const ulonglong2*>(&ks2[p * KS2 + tx * 4 + 2]);
#pragma unroll
                for (int i = 0; i < 4; i++) {
                    uint64_t a = sp ? qp[i].y : qp[i].x;
                    fma2(s2[i][0], a, k01.x); fma2(s2[i][1], a, k01.y);
                    fma2(s2[i][2], a, k23.x); fma2(s2[i][3], a, k23.y);
                }
            }
        }

        // Online softmax update (masking only at the global diagonal tile)
        const bool maskt = (t == nkv - 1);
        float pp[4][4];
#pragma unroll
        for (int i = 0; i < 4; i++) {
#pragma unroll
            for (int jn = 0; jn < 4; jn++) {
                float2 f = u2f(s2[i][jn]);
                pp[i][jn] = f.x + f.y;
            }
            if (maskt) {
                int qrow = q0 + ty * 4 + i;
#pragma unroll
                for (int jn = 0; jn < 4; jn++)
                    if (k0 + tx * 4 + jn > qrow) pp[i][jn] = -1e30f;
            }
            float mi = fmaxf(fmaxf(pp[i][0], pp[i][1]), fmaxf(pp[i][2], pp[i][3]));
#pragma unroll
            for (int off = 8; off > 0; off >>= 1)
                mi = fmaxf(mi, __shfl_xor_sync(0xffffffffu, mi, off));
            float mnew = fmaxf(m[i], mi);
            float alpha = __expf(m[i] - mnew);
            float rs = 0.0f;
#pragma unroll
            for (int jn = 0; jn < 4; jn++) {
                float p = __expf(pp[i][jn] - mnew);
                pp[i][jn] = p;
                rs += p;
            }
#pragma unroll
            for (int off = 8; off > 0; off >>= 1)
                rs += __shfl_xor_sync(0xffffffffu, rs, off);
            l[i] = l[i] * alpha + rs;
            m[i] = mnew;
            uint64_t a2 = f2u(alpha, alpha);
            mul2(o2[i][0], a2); mul2(o2[i][1], a2);
            mul2(o2[i][2], a2); mul2(o2[i][3], a2);
        }

        // P store (row-major, conflict-free); same-warp produce/consume
#pragma unroll
        for (int i = 0; i < 4; i++)
            *reinterpret_cast<float4*>(&ps[(ty * 4 + i) * TSF + tx * 4]) =
                make_float4(pp[i][0], pp[i][1], pp[i][2], pp[i][3]);
        __syncwarp();

        // GEMM2: O += P @ V, contraction over s in pairs. No splats.
#pragma unroll
        for (int pg = 0; pg < 16; pg++) {
            ulonglong2 pv[4];
#pragma unroll
            for (int i = 0; i < 4; i++)
                pv[i] = *reinterpret_cast<const ulonglong2*>(&ps[(ty * 4 + i) * TSF + pg * 4]);
#pragma unroll
            for (int sp = 0; sp < 2; sp++) {
                const int p = pg * 2 + sp;
                ulonglong2 v01 = *reinterpret_cast<const ulonglong2*>(&vs2[p * KS2 + tx * 4]);
                ulonglong2 v23 = *reinterpret_cast<const ulonglong2*>(&vs2[p * KS2 + tx * 4 + 2]);
#pragma unroll
                for (int i = 0; i < 4; i++) {
                    uint64_t a = sp ? pv[i].y : pv[i].x;
                    fma2(o2[i][0], a, v01.x); fma2(o2[i][1], a, v01.y);
                    fma2(o2[i][2], a, v23.x); fma2(o2[i][3], a, v23.y);
                }
            }
        }
    }

    // Epilogue: write UNNORMALIZED partial O (halves summed) + (m, l)
    const int base = ((b * NS + split) * 128 + j) * 32;
#pragma unroll
    for (int i = 0; i < 4; i++) {
        const int r = ty * 4 + i;
        float2 f0 = u2f(o2[i][0]), f1 = u2f(o2[i][1]);
        float2 f2_ = u2f(o2[i][2]), f3 = u2f(o2[i][3]);
        float4 o = make_float4(f0.x + f0.y, f1.x + f1.y, f2_.x + f2_.y, f3.x + f3.y);
        *reinterpret_cast<float4*>(&g_Opart[(base + r) * DK + tx * 4]) = o;
        if (tx == 0) g_ml[base + r] = make_float2(m[i], l[i]);
    }
}

// =====================================================================
// Kernel 3: combine partials. grid = (128, 4), block = 128.
// =====================================================================
__global__ __launch_bounds__(128) void combine_kernel(float* __restrict__ out)
{
    const int j = blockIdx.x, b = blockIdx.y;
    const int tid = threadIdx.x;
    const int r = tid >> 2;
    const int c0 = (tid & 3) * 16;
    const int nkv = (j >> 1) + 1;
    const int per = (nkv + NS - 1) / NS;
    const int nsp = (nkv + per - 1) / per;   // non-empty splits

    float mv[NS], lv[NS];
    float M = -1e30f;
    for (int s = 0; s < nsp; s++) {
        float2 ml = g_ml[((b * NS + s) * 128 + j) * 32 + r];
        mv[s] = ml.x; lv[s] = ml.y;
        M = fmaxf(M, mv[s]);
    }
    float L = 0.0f, w[NS];
    for (int s = 0; s < nsp; s++) {
        w[s] = __expf(mv[s] - M);
        L += w[s] * lv[s];
    }
    const float inv = 1.0f / L;

    float4 acc[4];
#pragma unroll
    for (int q = 0; q < 4; q++) acc[q] = make_float4(0.f, 0.f, 0.f, 0.f);

    for (int s = 0; s < nsp; s++) {
        const float* Op = &g_Opart[(((b * NS + s) * 128 + j) * 32 + r) * DK + c0];
        const float ws = w[s];
#pragma unroll
        for (int q = 0; q < 4; q++) {
            float4 v = *reinterpret_cast<const float4*>(Op + q * 4);
            acc[q].x += ws * v.x; acc[q].y += ws * v.y;
            acc[q].z += ws * v.z; acc[q].w += ws * v.w;
        }
    }

    float* op = &out[((b * S_) + j * 32 + r) * DK + c0];
#pragma unroll
    for (int q = 0; q < 4; q++) {
        float4 v = make_float4(acc[q].x * inv, acc[q].y * inv,
                               acc[q].z * inv, acc[q].w * inv);
        *reinterpret_cast<float4*>(op + q * 4) = v;
    }
}

// =====================================================================
extern "C" void kernel_launch(void* const* d_in, const int* in_sizes, int n_in,
                              void* d_out, int out_size)
{
    const float* x  = (const float*)d_in[0];
    const float* WQ = (const float*)d_in[1];
    const float* WK = (const float*)d_in[2];
    const float* WV = (const float*)d_in[3];
    float* out = (float*)d_out;

    (void)in_sizes; (void)n_in; (void)out_size;

    cudaFuncSetAttribute(attn_kernel, cudaFuncAttributeMaxDynamicSharedMemorySize, SMEM_TOTAL);

    proj_kernel<<<256, 256>>>(x, WQ, WK, WV);
    attn_kernel<<<dim3(128, 4, NS), 128, SMEM_TOTAL>>>();
    combine_kernel<<<dim3(128, 4), 128>>>(out);
}

// round 6
// speedup vs baseline: 1.3298x; 1.3298x over previous
#include <cuda_runtime.h>
#include <cstdint>

#define B_  4
#define S_  4096
#define DM  768
#define DK  64
#define NS  8          // KV splits per q-tile

// Scratch (device globals: no allocation allowed)
__device__ float  g_Q [B_ * S_ * DK];   // [b*S+s][d]  (pre-scaled by 1/8)
__device__ float  g_Kt[B_ * DK * S_];   // [b][d][s]   (K transposed)
__device__ float  g_V [B_ * S_ * DK];   // [b*S+s][d]
__device__ float  g_Opart[B_ * NS * 128 * 32 * DK];  // unnormalized partial O
__device__ float2 g_ml   [B_ * NS * 128 * 32];       // per-row (m, l) per split

// ---------------- packed f32x2 helpers (FFMA2 path, sm_100+) ----------------
__device__ __forceinline__ void fma2(uint64_t& acc, uint64_t a, uint64_t b) {
    asm("fma.rn.f32x2 %0, %1, %2, %0;" : "+l"(acc) : "l"(a), "l"(b));
}
__device__ __forceinline__ void mul2(uint64_t& acc, uint64_t a) {
    asm("mul.rn.f32x2 %0, %0, %1;" : "+l"(acc) : "l"(a));
}
__device__ __forceinline__ uint64_t f2u(float x, float y) {
    uint64_t v; asm("mov.b64 %0, {%1,%2};" : "=l"(v) : "f"(x), "f"(y)); return v;
}
__device__ __forceinline__ float2 u2f(uint64_t v) {
    float2 f; asm("mov.b64 {%0,%1}, %2;" : "=f"(f.x), "=f"(f.y) : "l"(v)); return f;
}

// =====================================================================
// Kernel 1: QKV projection, one W per block. grid = (256, 3), block = 256.
// Block (bx, w) computes rows bx*64..+63 of X @ W_w. 768 blocks -> 5.2/SM.
// x is re-read per w but stays L2-resident (48 MB < 126 MB L2).
// K (w==1) is written TRANSPOSED to g_Kt[b][d][s]; Q pre-scaled by 0.125.
// =====================================================================
#define XS_STRIDE 20    // floats per x row (16 + 4 pad)
#define WS_STRIDE 68    // floats per kk row (64 + 4 pad)

__global__ __launch_bounds__(256) void proj_kernel(
    const float* __restrict__ x,
    const float* __restrict__ WQ,
    const float* __restrict__ WK,
    const float* __restrict__ WV)
{
    __shared__ float xs[64 * XS_STRIDE];   // [r][kk]
    __shared__ float ws[16 * WS_STRIDE];   // [kk][n]

    const int tid = threadIdx.x;
    const int ty = tid >> 4;        // 0..15 -> rows ty*4..+3
    const int tx = tid & 15;        // 0..15 -> cols tx*4..+3
    const int row0 = blockIdx.x * 64;
    const int w = blockIdx.y;
    const float* __restrict__ W = (w == 0) ? WQ : ((w == 1) ? WK : WV);

    const int xr_r = tid >> 2, xr_c = tid & 3;        // x: 64 rows x 4 float4
    const int w_kk = tid >> 4, w_n4 = tid & 15;       // W: 16 kk x 16 float4

    float4 xr = *reinterpret_cast<const float4*>(&x[(row0 + xr_r) * DM + xr_c * 4]);
    float4 wr = *reinterpret_cast<const float4*>(&W[w_kk * DK + w_n4 * 4]);

    uint64_t acc[4][2];
#pragma unroll
    for (int i = 0; i < 4; i++) { acc[i][0] = 0ull; acc[i][1] = 0ull; }

    for (int k0 = 0; k0 < DM; k0 += 16) {
        __syncthreads();
        *reinterpret_cast<float4*>(&xs[xr_r * XS_STRIDE + xr_c * 4]) = xr;
        *reinterpret_cast<float4*>(&ws[w_kk * WS_STRIDE + w_n4 * 4]) = wr;
        __syncthreads();

        if (k0 + 16 < DM) {
            xr = *reinterpret_cast<const float4*>(&x[(row0 + xr_r) * DM + k0 + 16 + xr_c * 4]);
            wr = *reinterpret_cast<const float4*>(&W[(k0 + 16 + w_kk) * DK + w_n4 * 4]);
        }

#pragma unroll
        for (int kg = 0; kg < 4; kg++) {
            float4 av[4];
#pragma unroll
            for (int i = 0; i < 4; i++)
                av[i] = *reinterpret_cast<const float4*>(&xs[(ty * 4 + i) * XS_STRIDE + kg * 4]);
#pragma unroll
            for (int sub = 0; sub < 4; sub++) {
                const int kk = kg * 4 + sub;
                ulonglong2 bb = *reinterpret_cast<const ulonglong2*>(&ws[kk * WS_STRIDE + tx * 4]);
#pragma unroll
                for (int i = 0; i < 4; i++) {
                    float q = (&av[i].x)[sub];
                    uint64_t a = f2u(q, q);
                    fma2(acc[i][0], a, bb.x); fma2(acc[i][1], a, bb.y);
                }
            }
        }
    }

    // Epilogue (per-W destination)
    if (w == 0) {
#pragma unroll
        for (int i = 0; i < 4; i++) {
            const int r = row0 + ty * 4 + i;
            float2 qa = u2f(acc[i][0]), qb = u2f(acc[i][1]);
            *reinterpret_cast<float4*>(&g_Q[r * DK + tx * 4]) =
                make_float4(qa.x * 0.125f, qa.y * 0.125f, qb.x * 0.125f, qb.y * 0.125f);
        }
    } else if (w == 2) {
#pragma unroll
        for (int i = 0; i < 4; i++) {
            const int r = row0 + ty * 4 + i;
            float2 va = u2f(acc[i][0]), vb = u2f(acc[i][1]);
            *reinterpret_cast<float4*>(&g_V[r * DK + tx * 4]) =
                make_float4(va.x, va.y, vb.x, vb.y);
        }
    } else {
        // K: transpose 4x4 micro-tile in registers, write to g_Kt[b][d][s]
        const int b  = row0 >> 12;
        const int s0 = row0 & (S_ - 1);
        float kv[4][4];
#pragma unroll
        for (int i = 0; i < 4; i++) {
            float2 ka = u2f(acc[i][0]), kb = u2f(acc[i][1]);
            kv[i][0] = ka.x; kv[i][1] = ka.y; kv[i][2] = kb.x; kv[i][3] = kb.y;
        }
#pragma unroll
        for (int c = 0; c < 4; c++) {
            float4 kc = make_float4(kv[0][c], kv[1][c], kv[2][c], kv[3][c]);
            *reinterpret_cast<float4*>(&g_Kt[(b * DK + tx * 4 + c) * S_ + s0 + ty * 4]) = kc;
        }
    }
}

// =====================================================================
// Kernel 2: split-KV causal flash attention. grid = (128, 4, NS), block = 128.
// q-tile j = blockIdx.x (BQ=32); split = blockIdx.z handles KV tiles
// [t0, t1) with per = ceil(nkv/NS) (max 9 tiles -> balanced blocks).
// Writes UNNORMALIZED partial O + (m, l) per row per split.
// 52KB smem + 128 regs -> 4 co-resident blocks/SM = 16 warps/SM.
// =====================================================================
#define TS 68                       // padded tile stride (floats)
#define OFF_QS 0                    // qs [32][TS]
#define OFF_KS (32 * TS)            // ks [64 d][TS keys]
#define OFF_VS (OFF_KS + 64 * TS)   // vs [64 s][TS d]
#define OFF_PS (OFF_VS + 64 * TS)   // ps [32 r][TS s]
#define SMEM_TOTAL ((OFF_PS + 32 * TS) * 4)   // 52224 bytes

__global__ __launch_bounds__(128, 4) void attn_kernel()
{
    extern __shared__ float sm[];
    float* qs = sm + OFF_QS;
    float* ks = sm + OFF_KS;
    float* vs = sm + OFF_VS;
    float* ps = sm + OFF_PS;

    const int tid = threadIdx.x;
    const int ty = tid >> 4;   // 0..7  -> rows ty*4..+3
    const int tx = tid & 15;   // 0..15 -> cols tx*4..+3
    const int b = blockIdx.y;
    const int j = blockIdx.x;
    const int split = blockIdx.z;
    const int q0 = j * 32;
    const int nkv = (j >> 1) + 1;
    const int per = (nkv + NS - 1) / NS;
    const int t0 = split * per;
    const int t1 = min(nkv, t0 + per);
    if (t0 >= t1) return;   // empty split (uniform across block)

    const float* __restrict__ Qb  = g_Q  + b * (S_ * DK);
    const float* __restrict__ Ktb = g_Kt + b * (DK * S_);
    const float* __restrict__ Vb  = g_V  + b * (S_ * DK);

    // Load Q tile (32 x 64) row-major, already scaled
#pragma unroll
    for (int i = 0; i < 4; i++) {
        int lin = tid + i * 128;
        int d4 = lin & 15, r = lin >> 4;
        *reinterpret_cast<float4*>(&qs[r * TS + d4 * 4]) =
            *reinterpret_cast<const float4*>(&Qb[(q0 + r) * DK + d4 * 4]);
    }

    uint64_t o2[4][2];
    float m[4], l[4];
#pragma unroll
    for (int i = 0; i < 4; i++) {
        o2[i][0] = 0ull; o2[i][1] = 0ull;
        m[i] = -1e30f; l[i] = 0.0f;
    }

    for (int t = t0; t < t1; t++) {
        const int k0 = t * 64;
        __syncthreads();   // ks/vs free for reuse (also covers qs on first iter)

        // K tile: ks[d][key] straight from g_Kt; V tile: vs[s][d]
#pragma unroll
        for (int i = 0; i < 8; i++) {
            int lin = tid + i * 128;
            int c4 = lin & 15, rr = lin >> 4;
            *reinterpret_cast<float4*>(&ks[rr * TS + c4 * 4]) =
                *reinterpret_cast<const float4*>(&Ktb[rr * S_ + k0 + c4 * 4]);
            *reinterpret_cast<float4*>(&vs[rr * TS + c4 * 4]) =
                *reinterpret_cast<const float4*>(&Vb[(k0 + rr) * DK + c4 * 4]);
        }
        __syncthreads();

        // GEMM1: S = Q @ K^T (contract over d)
        uint64_t s2[4][2];
#pragma unroll
        for (int i = 0; i < 4; i++) { s2[i][0] = 0ull; s2[i][1] = 0ull; }
#pragma unroll
        for (int d0 = 0; d0 < 64; d0 += 4) {
            float4 qv[4];
#pragma unroll
            for (int i = 0; i < 4; i++)
                qv[i] = *reinterpret_cast<const float4*>(&qs[(ty * 4 + i) * TS + d0]);
#pragma unroll
            for (int sub = 0; sub < 4; sub++) {
                ulonglong2 kk = *reinterpret_cast<const ulonglong2*>(&ks[(d0 + sub) * TS + tx * 4]);
#pragma unroll
                for (int i = 0; i < 4; i++) {
                    float q = (&qv[i].x)[sub];
                    uint64_t a = f2u(q, q);
                    fma2(s2[i][0], a, kk.x); fma2(s2[i][1], a, kk.y);
                }
            }
        }

        // Online softmax update (masking only at the global diagonal tile)
        const bool maskt = (t == nkv - 1);
        float pp[4][4];
#pragma unroll
        for (int i = 0; i < 4; i++) {
            float2 a = u2f(s2[i][0]);
            float2 c = u2f(s2[i][1]);
            pp[i][0] = a.x; pp[i][1] = a.y; pp[i][2] = c.x; pp[i][3] = c.y;
            if (maskt) {
                int qrow = q0 + ty * 4 + i;
#pragma unroll
                for (int jn = 0; jn < 4; jn++)
                    if (k0 + tx * 4 + jn > qrow) pp[i][jn] = -1e30f;
            }
            float mi = fmaxf(fmaxf(pp[i][0], pp[i][1]), fmaxf(pp[i][2], pp[i][3]));
#pragma unroll
            for (int off = 8; off > 0; off >>= 1)
                mi = fmaxf(mi, __shfl_xor_sync(0xffffffffu, mi, off));
            float mnew = fmaxf(m[i], mi);
            float alpha = __expf(m[i] - mnew);
            float rs = 0.0f;
#pragma unroll
            for (int jn = 0; jn < 4; jn++) {
                float p = __expf(pp[i][jn] - mnew);
                pp[i][jn] = p;
                rs += p;
            }
#pragma unroll
            for (int off = 8; off > 0; off >>= 1)
                rs += __shfl_xor_sync(0xffffffffu, rs, off);
            l[i] = l[i] * alpha + rs;
            m[i] = mnew;
            uint64_t a2 = f2u(alpha, alpha);
            mul2(o2[i][0], a2); mul2(o2[i][1], a2);
        }

        // P store (row-major, conflict-free); same-warp produce/consume
#pragma unroll
        for (int i = 0; i < 4; i++)
            *reinterpret_cast<float4*>(&ps[(ty * 4 + i) * TS + tx * 4]) =
                make_float4(pp[i][0], pp[i][1], pp[i][2], pp[i][3]);
        __syncwarp();

        // GEMM2: O += P @ V (contract over s)
#pragma unroll
        for (int s0 = 0; s0 < 64; s0 += 4) {
            float4 pv[4];
#pragma unroll
            for (int i = 0; i < 4; i++)
                pv[i] = *reinterpret_cast<const float4*>(&ps[(ty * 4 + i) * TS + s0]);
#pragma unroll
            for (int sub = 0; sub < 4; sub++) {
                ulonglong2 vv = *reinterpret_cast<const ulonglong2*>(&vs[(s0 + sub) * TS + tx * 4]);
#pragma unroll
                for (int i = 0; i < 4; i++) {
                    float p = (&pv[i].x)[sub];
                    uint64_t a = f2u(p, p);
                    fma2(o2[i][0], a, vv.x); fma2(o2[i][1], a, vv.y);
                }
            }
        }
    }

    // Epilogue: write UNNORMALIZED partial O + (m, l)
    const int base = ((b * NS + split) * 128 + j) * 32;
#pragma unroll
    for (int i = 0; i < 4; i++) {
        const int r = ty * 4 + i;
        ulonglong2 o; o.x = o2[i][0]; o.y = o2[i][1];
        *reinterpret_cast<ulonglong2*>(&g_Opart[(base + r) * DK + tx * 4]) = o;
        if (tx == 0) g_ml[base + r] = make_float2(m[i], l[i]);
    }
}

// =====================================================================
// Kernel 3: combine partials. grid = (128, 4), block = 128.
// Thread handles one row-quarter: r = tid>>2 (0..31), 16 cols.
// =====================================================================
__global__ __launch_bounds__(128) void combine_kernel(float* __restrict__ out)
{
    const int j = blockIdx.x, b = blockIdx.y;
    const int tid = threadIdx.x;
    const int r = tid >> 2;
    const int c0 = (tid & 3) * 16;
    const int nkv = (j >> 1) + 1;
    const int per = (nkv + NS - 1) / NS;
    const int nsp = (nkv + per - 1) / per;   // non-empty splits

    float mv[NS], lv[NS];
    float M = -1e30f;
    for (int s = 0; s < nsp; s++) {
        float2 ml = g_ml[((b * NS + s) * 128 + j) * 32 + r];
        mv[s] = ml.x; lv[s] = ml.y;
        M = fmaxf(M, mv[s]);
    }
    float L = 0.0f, w[NS];
    for (int s = 0; s < nsp; s++) {
        w[s] = __expf(mv[s] - M);
        L += w[s] * lv[s];
    }
    const float inv = 1.0f / L;

    float4 acc[4];
#pragma unroll
    for (int q = 0; q < 4; q++) acc[q] = make_float4(0.f, 0.f, 0.f, 0.f);

    for (int s = 0; s < nsp; s++) {
        const float* Op = &g_Opart[(((b * NS + s) * 128 + j) * 32 + r) * DK + c0];
        const float ws = w[s];
#pragma unroll
        for (int q = 0; q < 4; q++) {
            float4 v = *reinterpret_cast<const float4*>(Op + q * 4);
            acc[q].x += ws * v.x; acc[q].y += ws * v.y;
            acc[q].z += ws * v.z; acc[q].w += ws * v.w;
        }
    }

    float* op = &out[((b * S_) + j * 32 + r) * DK + c0];
#pragma unroll
    for (int q = 0; q < 4; q++) {
        float4 v = make_float4(acc[q].x * inv, acc[q].y * inv,
                               acc[q].z * inv, acc[q].w * inv);
        *reinterpret_cast<float4*>(op + q * 4) = v;
    }
}

// =====================================================================
extern "C" void kernel_launch(void* const* d_in, const int* in_sizes, int n_in,
                              void* d_out, int out_size)
{
    const float* x  = (const float*)d_in[0];
    const float* WQ = (const float*)d_in[1];
    const float* WK = (const float*)d_in[2];
    const float* WV = (const float*)d_in[3];
    float* out = (float*)d_out;

    (void)in_sizes; (void)n_in; (void)out_size;

    cudaFuncSetAttribute(attn_kernel, cudaFuncAttributeMaxDynamicSharedMemorySize, SMEM_TOTAL);

    proj_kernel<<<dim3(256, 3), 256>>>(x, WQ, WK, WV);
    attn_kernel<<<dim3(128, 4, NS), 128, SMEM_TOTAL>>>();
    combine_kernel<<<dim3(128, 4), 128>>>(out);
}

// round 7
// speedup vs baseline: 1.4209x; 1.0685x over previous
#include <cuda_runtime.h>
#include <cstdint>

#define B_  4
#define S_  4096
#define DM  768
#define DK  64
#define NS  8          // KV splits per q-tile

// Scratch (device globals: no allocation allowed)
__device__ float  g_Q [B_ * S_ * DK];   // [b*S+s][d]  (pre-scaled by 1/8)
__device__ float  g_Kt[B_ * DK * S_];   // [b][d][s]   (K transposed)
__device__ float  g_V [B_ * S_ * DK];   // [b*S+s][d]
__device__ float  g_Opart[B_ * NS * 128 * 32 * DK];  // unnormalized partial O
__device__ float2 g_ml   [B_ * NS * 128 * 32];       // per-row (m, l) per split

// ---------------- packed f32x2 helpers (FFMA2 path, sm_100+) ----------------
__device__ __forceinline__ void fma2(uint64_t& acc, uint64_t a, uint64_t b) {
    asm("fma.rn.f32x2 %0, %1, %2, %0;" : "+l"(acc) : "l"(a), "l"(b));
}
__device__ __forceinline__ void mul2(uint64_t& acc, uint64_t a) {
    asm("mul.rn.f32x2 %0, %0, %1;" : "+l"(acc) : "l"(a));
}
__device__ __forceinline__ uint64_t f2u(float x, float y) {
    uint64_t v; asm("mov.b64 %0, {%1,%2};" : "=l"(v) : "f"(x), "f"(y)); return v;
}
__device__ __forceinline__ float2 u2f(uint64_t v) {
    float2 f; asm("mov.b64 {%0,%1}, %2;" : "=f"(f.x), "=f"(f.y) : "l"(v)); return f;
}

// =====================================================================
// Kernel 1: fused QKV projection. grid = 256, block = 256. (round-4 winner)
// One block computes a 64-row stripe of Q, K, V together (x read ONCE;
// each xs SMEM read feeds 3 W's -> high FMA2 per crossbar byte).
// K is written TRANSPOSED to g_Kt[b][d][s]; Q is pre-scaled by 0.125.
// =====================================================================
#define XS_STRIDE 20    // floats per x row (16 + 4 pad)
#define WS_STRIDE 208   // floats per kk row (3*68 + 4 pad)

__global__ __launch_bounds__(256) void proj_kernel(
    const float* __restrict__ x,
    const float* __restrict__ WQ,
    const float* __restrict__ WK,
    const float* __restrict__ WV)
{
    __shared__ float xs[64 * XS_STRIDE];   // [r][kk]
    __shared__ float ws[16 * WS_STRIDE];   // [kk][w*68 + n]

    const int tid = threadIdx.x;
    const int ty = tid >> 4;        // 0..15 -> rows ty*4..+3
    const int tx = tid & 15;        // 0..15 -> cols tx*4..+3
    const int row0 = blockIdx.x * 64;

    const float* __restrict__ Wp0 = WQ;
    const float* __restrict__ Wp1 = WK;
    const float* __restrict__ Wp2 = WV;

    const int xr_r = tid >> 2, xr_c = tid & 3;        // x: 64 rows x 4 float4
    const int w_kk = tid >> 4, w_n4 = tid & 15;       // W: 16 kk x 16 float4 (per W)

    float4 xr = *reinterpret_cast<const float4*>(&x[(row0 + xr_r) * DM + xr_c * 4]);
    float4 wr0 = *reinterpret_cast<const float4*>(&Wp0[w_kk * DK + w_n4 * 4]);
    float4 wr1 = *reinterpret_cast<const float4*>(&Wp1[w_kk * DK + w_n4 * 4]);
    float4 wr2 = *reinterpret_cast<const float4*>(&Wp2[w_kk * DK + w_n4 * 4]);

    uint64_t acc[3][4][2];
#pragma unroll
    for (int w = 0; w < 3; w++)
#pragma unroll
        for (int i = 0; i < 4; i++) { acc[w][i][0] = 0ull; acc[w][i][1] = 0ull; }

    for (int k0 = 0; k0 < DM; k0 += 16) {
        __syncthreads();
        *reinterpret_cast<float4*>(&xs[xr_r * XS_STRIDE + xr_c * 4]) = xr;
        *reinterpret_cast<float4*>(&ws[w_kk * WS_STRIDE + 0 * 68 + w_n4 * 4]) = wr0;
        *reinterpret_cast<float4*>(&ws[w_kk * WS_STRIDE + 1 * 68 + w_n4 * 4]) = wr1;
        *reinterpret_cast<float4*>(&ws[w_kk * WS_STRIDE + 2 * 68 + w_n4 * 4]) = wr2;
        __syncthreads();

        if (k0 + 16 < DM) {
            xr  = *reinterpret_cast<const float4*>(&x[(row0 + xr_r) * DM + k0 + 16 + xr_c * 4]);
            wr0 = *reinterpret_cast<const float4*>(&Wp0[(k0 + 16 + w_kk) * DK + w_n4 * 4]);
            wr1 = *reinterpret_cast<const float4*>(&Wp1[(k0 + 16 + w_kk) * DK + w_n4 * 4]);
            wr2 = *reinterpret_cast<const float4*>(&Wp2[(k0 + 16 + w_kk) * DK + w_n4 * 4]);
        }

#pragma unroll
        for (int kg = 0; kg < 4; kg++) {
            float4 av[4];
#pragma unroll
            for (int i = 0; i < 4; i++)
                av[i] = *reinterpret_cast<const float4*>(&xs[(ty * 4 + i) * XS_STRIDE + kg * 4]);
#pragma unroll
            for (int sub = 0; sub < 4; sub++) {
                const int kk = kg * 4 + sub;
                ulonglong2 b0 = *reinterpret_cast<const ulonglong2*>(&ws[kk * WS_STRIDE + 0 * 68 + tx * 4]);
                ulonglong2 b1 = *reinterpret_cast<const ulonglong2*>(&ws[kk * WS_STRIDE + 1 * 68 + tx * 4]);
                ulonglong2 b2 = *reinterpret_cast<const ulonglong2*>(&ws[kk * WS_STRIDE + 2 * 68 + tx * 4]);
#pragma unroll
                for (int i = 0; i < 4; i++) {
                    float q = (&av[i].x)[sub];
                    uint64_t a = f2u(q, q);
                    fma2(acc[0][i][0], a, b0.x); fma2(acc[0][i][1], a, b0.y);
                    fma2(acc[1][i][0], a, b1.x); fma2(acc[1][i][1], a, b1.y);
                    fma2(acc[2][i][0], a, b2.x); fma2(acc[2][i][1], a, b2.y);
                }
            }
        }
    }

    // Epilogue
    const int b  = row0 >> 12;
    const int s0 = row0 & (S_ - 1);
    float kv[4][4];
#pragma unroll
    for (int i = 0; i < 4; i++) {
        const int r = row0 + ty * 4 + i;
        float2 qa = u2f(acc[0][i][0]), qb = u2f(acc[0][i][1]);
        float4 qo = make_float4(qa.x * 0.125f, qa.y * 0.125f, qb.x * 0.125f, qb.y * 0.125f);
        *reinterpret_cast<float4*>(&g_Q[r * DK + tx * 4]) = qo;
        float2 va = u2f(acc[2][i][0]), vb = u2f(acc[2][i][1]);
        *reinterpret_cast<float4*>(&g_V[r * DK + tx * 4]) = make_float4(va.x, va.y, vb.x, vb.y);
        float2 ka = u2f(acc[1][i][0]), kb = u2f(acc[1][i][1]);
        kv[i][0] = ka.x; kv[i][1] = ka.y; kv[i][2] = kb.x; kv[i][3] = kb.y;
    }
#pragma unroll
    for (int c = 0; c < 4; c++) {
        float4 kc = make_float4(kv[0][c], kv[1][c], kv[2][c], kv[3][c]);
        *reinterpret_cast<float4*>(&g_Kt[(b * DK + tx * 4 + c) * S_ + s0 + ty * 4]) = kc;
    }
}

// =====================================================================
// Kernel 2: split-KV causal flash attention. grid = (128, 4, NS), block = 128.
// SMEM overlay: ps reuses the ks region (ks dead after GEMM1; extra
// __syncthreads() after GEMM1 makes it safe). 43.5KB smem + <=102 regs
// (__launch_bounds__(128,5)) -> 5 blocks/SM = 20 warps/SM.
// =====================================================================
#define TS 68                       // padded tile stride (floats)
#define OFF_QS 0                    // qs [32][TS]            (8704 B)
#define OFF_KS (32 * TS)            // ks [64 d][TS keys]     (17408 B)
#define OFF_PS OFF_KS               // ps [32 r][TS s] OVERLAYS ks
#define OFF_VS (OFF_KS + 64 * TS)   // vs [64 s][TS d]        (17408 B)
#define SMEM_TOTAL ((OFF_VS + 64 * TS) * 4)   // 43520 bytes

__global__ __launch_bounds__(128, 5) void attn_kernel()
{
    extern __shared__ float sm[];
    float* qs = sm + OFF_QS;
    float* ks = sm + OFF_KS;
    float* vs = sm + OFF_VS;
    float* ps = sm + OFF_PS;   // overlays ks

    const int tid = threadIdx.x;
    const int ty = tid >> 4;   // 0..7  -> rows ty*4..+3
    const int tx = tid & 15;   // 0..15 -> cols tx*4..+3
    const int b = blockIdx.y;
    const int j = blockIdx.x;
    const int split = blockIdx.z;
    const int q0 = j * 32;
    const int nkv = (j >> 1) + 1;
    const int per = (nkv + NS - 1) / NS;
    const int t0 = split * per;
    const int t1 = min(nkv, t0 + per);
    if (t0 >= t1) return;   // empty split (uniform across block)

    const float* __restrict__ Qb  = g_Q  + b * (S_ * DK);
    const float* __restrict__ Ktb = g_Kt + b * (DK * S_);
    const float* __restrict__ Vb  = g_V  + b * (S_ * DK);

    // Load Q tile (32 x 64) row-major, already scaled
#pragma unroll
    for (int i = 0; i < 4; i++) {
        int lin = tid + i * 128;
        int d4 = lin & 15, r = lin >> 4;
        *reinterpret_cast<float4*>(&qs[r * TS + d4 * 4]) =
            *reinterpret_cast<const float4*>(&Qb[(q0 + r) * DK + d4 * 4]);
    }

    uint64_t o2[4][2];
    float m[4], l[4];
#pragma unroll
    for (int i = 0; i < 4; i++) {
        o2[i][0] = 0ull; o2[i][1] = 0ull;
        m[i] = -1e30f; l[i] = 0.0f;
    }

    for (int t = t0; t < t1; t++) {
        const int k0 = t * 64;
        __syncthreads();   // all GEMM2 readers done -> ks/ps/vs free

        // K tile: ks[d][key] straight from g_Kt; V tile: vs[s][d]
#pragma unroll
        for (int i = 0; i < 8; i++) {
            int lin = tid + i * 128;
            int c4 = lin & 15, rr = lin >> 4;
            *reinterpret_cast<float4*>(&ks[rr * TS + c4 * 4]) =
                *reinterpret_cast<const float4*>(&Ktb[rr * S_ + k0 + c4 * 4]);
            *reinterpret_cast<float4*>(&vs[rr * TS + c4 * 4]) =
                *reinterpret_cast<const float4*>(&Vb[(k0 + rr) * DK + c4 * 4]);
        }
        __syncthreads();

        // GEMM1: S = Q @ K^T (contract over d)
        uint64_t s2[4][2];
#pragma unroll
        for (int i = 0; i < 4; i++) { s2[i][0] = 0ull; s2[i][1] = 0ull; }
#pragma unroll
        for (int d0 = 0; d0 < 64; d0 += 4) {
            float4 qv[4];
#pragma unroll
            for (int i = 0; i < 4; i++)
                qv[i] = *reinterpret_cast<const float4*>(&qs[(ty * 4 + i) * TS + d0]);
#pragma unroll
            for (int sub = 0; sub < 4; sub++) {
                ulonglong2 kk = *reinterpret_cast<const ulonglong2*>(&ks[(d0 + sub) * TS + tx * 4]);
#pragma unroll
                for (int i = 0; i < 4; i++) {
                    float q = (&qv[i].x)[sub];
                    uint64_t a = f2u(q, q);
                    fma2(s2[i][0], a, kk.x); fma2(s2[i][1], a, kk.y);
                }
            }
        }

        __syncthreads();   // ks fully consumed by ALL warps -> ps may overlay it

        // Online softmax update (masking only at the global diagonal tile)
        const bool maskt = (t == nkv - 1);
        float pp[4][4];
#pragma unroll
        for (int i = 0; i < 4; i++) {
            float2 a = u2f(s2[i][0]);
            float2 c = u2f(s2[i][1]);
            pp[i][0] = a.x; pp[i][1] = a.y; pp[i][2] = c.x; pp[i][3] = c.y;
            if (maskt) {
                int qrow = q0 + ty * 4 + i;
#pragma unroll
                for (int jn = 0; jn < 4; jn++)
                    if (k0 + tx * 4 + jn > qrow) pp[i][jn] = -1e30f;
            }
            float mi = fmaxf(fmaxf(pp[i][0], pp[i][1]), fmaxf(pp[i][2], pp[i][3]));
#pragma unroll
            for (int off = 8; off > 0; off >>= 1)
                mi = fmaxf(mi, __shfl_xor_sync(0xffffffffu, mi, off));
            float mnew = fmaxf(m[i], mi);
            float alpha = __expf(m[i] - mnew);
            float rs = 0.0f;
#pragma unroll
            for (int jn = 0; jn < 4; jn++) {
                float p = __expf(pp[i][jn] - mnew);
                pp[i][jn] = p;
                rs += p;
            }
#pragma unroll
            for (int off = 8; off > 0; off >>= 1)
                rs += __shfl_xor_sync(0xffffffffu, rs, off);
            l[i] = l[i] * alpha + rs;
            m[i] = mnew;
            uint64_t a2 = f2u(alpha, alpha);
            mul2(o2[i][0], a2); mul2(o2[i][1], a2);
        }

        // P store (row-major, conflict-free); same-warp produce/consume
#pragma unroll
        for (int i = 0; i < 4; i++)
            *reinterpret_cast<float4*>(&ps[(ty * 4 + i) * TS + tx * 4]) =
                make_float4(pp[i][0], pp[i][1], pp[i][2], pp[i][3]);
        __syncwarp();

        // GEMM2: O += P @ V (contract over s)
#pragma unroll
        for (int s0 = 0; s0 < 64; s0 += 4) {
            float4 pv[4];
#pragma unroll
            for (int i = 0; i < 4; i++)
                pv[i] = *reinterpret_cast<const float4*>(&ps[(ty * 4 + i) * TS + s0]);
#pragma unroll
            for (int sub = 0; sub < 4; sub++) {
                ulonglong2 vv = *reinterpret_cast<const ulonglong2*>(&vs[(s0 + sub) * TS + tx * 4]);
#pragma unroll
                for (int i = 0; i < 4; i++) {
                    float p = (&pv[i].x)[sub];
                    uint64_t a = f2u(p, p);
                    fma2(o2[i][0], a, vv.x); fma2(o2[i][1], a, vv.y);
                }
            }
        }
    }

    // Epilogue: write UNNORMALIZED partial O + (m, l)
    const int base = ((b * NS + split) * 128 + j) * 32;
#pragma unroll
    for (int i = 0; i < 4; i++) {
        const int r = ty * 4 + i;
        ulonglong2 o; o.x = o2[i][0]; o.y = o2[i][1];
        *reinterpret_cast<ulonglong2*>(&g_Opart[(base + r) * DK + tx * 4]) = o;
        if (tx == 0) g_ml[base + r] = make_float2(m[i], l[i]);
    }
}

// =====================================================================
// Kernel 3: combine partials. grid = (128, 4), block = 128.
// Thread handles one row-quarter: r = tid>>2 (0..31), 16 cols.
// =====================================================================
__global__ __launch_bounds__(128) void combine_kernel(float* __restrict__ out)
{
    const int j = blockIdx.x, b = blockIdx.y;
    const int tid = threadIdx.x;
    const int r = tid >> 2;
    const int c0 = (tid & 3) * 16;
    const int nkv = (j >> 1) + 1;
    const int per = (nkv + NS - 1) / NS;
    const int nsp = (nkv + per - 1) / per;   // non-empty splits

    float mv[NS], lv[NS];
    float M = -1e30f;
    for (int s = 0; s < nsp; s++) {
        float2 ml = g_ml[((b * NS + s) * 128 + j) * 32 + r];
        mv[s] = ml.x; lv[s] = ml.y;
        M = fmaxf(M, mv[s]);
    }
    float L = 0.0f, w[NS];
    for (int s = 0; s < nsp; s++) {
        w[s] = __expf(mv[s] - M);
        L += w[s] * lv[s];
    }
    const float inv = 1.0f / L;

    float4 acc[4];
#pragma unroll
    for (int q = 0; q < 4; q++) acc[q] = make_float4(0.f, 0.f, 0.f, 0.f);

    for (int s = 0; s < nsp; s++) {
        const float* Op = &g_Opart[(((b * NS + s) * 128 + j) * 32 + r) * DK + c0];
        const float ws = w[s];
#pragma unroll
        for (int q = 0; q < 4; q++) {
            float4 v = *reinterpret_cast<const float4*>(Op + q * 4);
            acc[q].x += ws * v.x; acc[q].y += ws * v.y;
            acc[q].z += ws * v.z; acc[q].w += ws * v.w;
        }
    }

    float* op = &out[((b * S_) + j * 32 + r) * DK + c0];
#pragma unroll
    for (int q = 0; q < 4; q++) {
        float4 v = make_float4(acc[q].x * inv, acc[q].y * inv,
                               acc[q].z * inv, acc[q].w * inv);
        *reinterpret_cast<float4*>(op + q * 4) = v;
    }
}

// =====================================================================
extern "C" void kernel_launch(void* const* d_in, const int* in_sizes, int n_in,
                              void* d_out, int out_size)
{
    const float* x  = (const float*)d_in[0];
    const float* WQ = (const float*)d_in[1];
    const float* WK = (const float*)d_in[2];
    const float* WV = (const float*)d_in[3];
    float* out = (float*)d_out;

    (void)in_sizes; (void)n_in; (void)out_size;

    cudaFuncSetAttribute(attn_kernel, cudaFuncAttributeMaxDynamicSharedMemorySize, SMEM_TOTAL);

    proj_kernel<<<256, 256>>>(x, WQ, WK, WV);
    attn_kernel<<<dim3(128, 4, NS), 128, SMEM_TOTAL>>>();
    combine_kernel<<<dim3(128, 4), 128>>>(out);
}

// round 8
// speedup vs baseline: 1.4795x; 1.0413x over previous
#include <cuda_runtime.h>
#include <cstdint>

#define B_  4
#define S_  4096
#define DM  768
#define DK  64
#define NS  8          // KV splits per q-tile
#define NJ  64         // number of 64-row q-tiles per batch

// Scratch (device globals: no allocation allowed)
__device__ float  g_Q [B_ * S_ * DK];   // [b*S+s][d]  (pre-scaled by 1/8)
__device__ float  g_Kt[B_ * DK * S_];   // [b][d][s]   (K transposed)
__device__ float  g_V [B_ * S_ * DK];   // [b*S+s][d]
__device__ float  g_Opart[B_ * NS * NJ * 64 * DK];  // unnormalized partial O
__device__ float2 g_ml   [B_ * NS * NJ * 64];       // per-row (m, l) per split

// ---------------- packed f32x2 helpers (FFMA2 path, sm_100+) ----------------
__device__ __forceinline__ void fma2(uint64_t& acc, uint64_t a, uint64_t b) {
    asm("fma.rn.f32x2 %0, %1, %2, %0;" : "+l"(acc) : "l"(a), "l"(b));
}
__device__ __forceinline__ void mul2(uint64_t& acc, uint64_t a) {
    asm("mul.rn.f32x2 %0, %0, %1;" : "+l"(acc) : "l"(a));
}
__device__ __forceinline__ uint64_t f2u(float x, float y) {
    uint64_t v; asm("mov.b64 %0, {%1,%2};" : "=l"(v) : "f"(x), "f"(y)); return v;
}
__device__ __forceinline__ float2 u2f(uint64_t v) {
    float2 f; asm("mov.b64 {%0,%1}, %2;" : "=f"(f.x), "=f"(f.y) : "l"(v)); return f;
}

// =====================================================================
// Kernel 1: fused QKV projection. grid = 256, block = 256. (unchanged)
// One block computes a 64-row stripe of Q, K, V together (x read ONCE).
// K is written TRANSPOSED to g_Kt[b][d][s]; Q is pre-scaled by 0.125.
// =====================================================================
#define XS_STRIDE 20    // floats per x row (16 + 4 pad)
#define WS_STRIDE 208   // floats per kk row (3*68 + 4 pad)

__global__ __launch_bounds__(256) void proj_kernel(
    const float* __restrict__ x,
    const float* __restrict__ WQ,
    const float* __restrict__ WK,
    const float* __restrict__ WV)
{
    __shared__ float xs[64 * XS_STRIDE];   // [r][kk]
    __shared__ float ws[16 * WS_STRIDE];   // [kk][w*68 + n]

    const int tid = threadIdx.x;
    const int ty = tid >> 4;        // 0..15 -> rows ty*4..+3
    const int tx = tid & 15;        // 0..15 -> cols tx*4..+3
    const int row0 = blockIdx.x * 64;

    const float* __restrict__ Wp0 = WQ;
    const float* __restrict__ Wp1 = WK;
    const float* __restrict__ Wp2 = WV;

    const int xr_r = tid >> 2, xr_c = tid & 3;        // x: 64 rows x 4 float4
    const int w_kk = tid >> 4, w_n4 = tid & 15;       // W: 16 kk x 16 float4 (per W)

    float4 xr = *reinterpret_cast<const float4*>(&x[(row0 + xr_r) * DM + xr_c * 4]);
    float4 wr0 = *reinterpret_cast<const float4*>(&Wp0[w_kk * DK + w_n4 * 4]);
    float4 wr1 = *reinterpret_cast<const float4*>(&Wp1[w_kk * DK + w_n4 * 4]);
    float4 wr2 = *reinterpret_cast<const float4*>(&Wp2[w_kk * DK + w_n4 * 4]);

    uint64_t acc[3][4][2];
#pragma unroll
    for (int w = 0; w < 3; w++)
#pragma unroll
        for (int i = 0; i < 4; i++) { acc[w][i][0] = 0ull; acc[w][i][1] = 0ull; }

    for (int k0 = 0; k0 < DM; k0 += 16) {
        __syncthreads();
        *reinterpret_cast<float4*>(&xs[xr_r * XS_STRIDE + xr_c * 4]) = xr;
        *reinterpret_cast<float4*>(&ws[w_kk * WS_STRIDE + 0 * 68 + w_n4 * 4]) = wr0;
        *reinterpret_cast<float4*>(&ws[w_kk * WS_STRIDE + 1 * 68 + w_n4 * 4]) = wr1;
        *reinterpret_cast<float4*>(&ws[w_kk * WS_STRIDE + 2 * 68 + w_n4 * 4]) = wr2;
        __syncthreads();

        if (k0 + 16 < DM) {
            xr  = *reinterpret_cast<const float4*>(&x[(row0 + xr_r) * DM + k0 + 16 + xr_c * 4]);
            wr0 = *reinterpret_cast<const float4*>(&Wp0[(k0 + 16 + w_kk) * DK + w_n4 * 4]);
            wr1 = *reinterpret_cast<const float4*>(&Wp1[(k0 + 16 + w_kk) * DK + w_n4 * 4]);
            wr2 = *reinterpret_cast<const float4*>(&Wp2[(k0 + 16 + w_kk) * DK + w_n4 * 4]);
        }

#pragma unroll
        for (int kg = 0; kg < 4; kg++) {
            float4 av[4];
#pragma unroll
            for (int i = 0; i < 4; i++)
                av[i] = *reinterpret_cast<const float4*>(&xs[(ty * 4 + i) * XS_STRIDE + kg * 4]);
#pragma unroll
            for (int sub = 0; sub < 4; sub++) {
                const int kk = kg * 4 + sub;
                ulonglong2 b0 = *reinterpret_cast<const ulonglong2*>(&ws[kk * WS_STRIDE + 0 * 68 + tx * 4]);
                ulonglong2 b1 = *reinterpret_cast<const ulonglong2*>(&ws[kk * WS_STRIDE + 1 * 68 + tx * 4]);
                ulonglong2 b2 = *reinterpret_cast<const ulonglong2*>(&ws[kk * WS_STRIDE + 2 * 68 + tx * 4]);
#pragma unroll
                for (int i = 0; i < 4; i++) {
                    float q = (&av[i].x)[sub];
                    uint64_t a = f2u(q, q);
                    fma2(acc[0][i][0], a, b0.x); fma2(acc[0][i][1], a, b0.y);
                    fma2(acc[1][i][0], a, b1.x); fma2(acc[1][i][1], a, b1.y);
                    fma2(acc[2][i][0], a, b2.x); fma2(acc[2][i][1], a, b2.y);
                }
            }
        }
    }

    // Epilogue
    const int b  = row0 >> 12;
    const int s0 = row0 & (S_ - 1);
    float kv[4][4];
#pragma unroll
    for (int i = 0; i < 4; i++) {
        const int r = row0 + ty * 4 + i;
        float2 qa = u2f(acc[0][i][0]), qb = u2f(acc[0][i][1]);
        float4 qo = make_float4(qa.x * 0.125f, qa.y * 0.125f, qb.x * 0.125f, qb.y * 0.125f);
        *reinterpret_cast<float4*>(&g_Q[r * DK + tx * 4]) = qo;
        float2 va = u2f(acc[2][i][0]), vb = u2f(acc[2][i][1]);
        *reinterpret_cast<float4*>(&g_V[r * DK + tx * 4]) = make_float4(va.x, va.y, vb.x, vb.y);
        float2 ka = u2f(acc[1][i][0]), kb = u2f(acc[1][i][1]);
        kv[i][0] = ka.x; kv[i][1] = ka.y; kv[i][2] = kb.x; kv[i][3] = kb.y;
    }
#pragma unroll
    for (int c = 0; c < 4; c++) {
        float4 kc = make_float4(kv[0][c], kv[1][c], kv[2][c], kv[3][c]);
        *reinterpret_cast<float4*>(&g_Kt[(b * DK + tx * 4 + c) * S_ + s0 + ty * 4]) = kc;
    }
}

// =====================================================================
// Kernel 2: split-KV causal flash attention, BQ=64.
// grid = (NJ, 4, NS), block = 128. Thread (ty 0..7, tx 0..15) owns
// 8 rows x 4 cols of the 64x64 S / 64x64 O tiles -> K/V SMEM reads
// amortized over 2x the FMA work (crossbar no longer co-binding).
// ps overlays ks (extra barrier after GEMM1). 52.2KB smem + <=128 regs
// -> 4 blocks/SM = 16 warps/SM.
// =====================================================================
#define TS 68                       // padded tile stride (floats)
#define OFF_QS 0                    // qs [64][TS]            (17408 B)
#define OFF_KS (64 * TS)            // ks [64 d][TS keys]     (17408 B)
#define OFF_PS OFF_KS               // ps [64 r][TS s] OVERLAYS ks
#define OFF_VS (OFF_KS + 64 * TS)   // vs [64 s][TS d]        (17408 B)
#define SMEM_TOTAL ((OFF_VS + 64 * TS) * 4)   // 52224 bytes

__global__ __launch_bounds__(128, 4) void attn_kernel()
{
    extern __shared__ float sm[];
    float* qs = sm + OFF_QS;
    float* ks = sm + OFF_KS;
    float* vs = sm + OFF_VS;
    float* ps = sm + OFF_PS;   // overlays ks

    const int tid = threadIdx.x;
    const int ty = tid >> 4;   // 0..7  -> rows ty*8..+7
    const int tx = tid & 15;   // 0..15 -> cols tx*4..+3
    const int b = blockIdx.y;
    const int j = blockIdx.x;            // 64-row q-tile index
    const int split = blockIdx.z;
    const int q0 = j * 64;
    const int nkv = j + 1;               // KV tiles of 64 keys
    const int per = (nkv + NS - 1) / NS;
    const int t0 = split * per;
    const int t1 = min(nkv, t0 + per);
    if (t0 >= t1) return;   // empty split (uniform across block)

    const float* __restrict__ Qb  = g_Q  + b * (S_ * DK);
    const float* __restrict__ Ktb = g_Kt + b * (DK * S_);
    const float* __restrict__ Vb  = g_V  + b * (S_ * DK);

    // Load Q tile (64 x 64) row-major, already scaled
#pragma unroll
    for (int i = 0; i < 8; i++) {
        int lin = tid + i * 128;
        int d4 = lin & 15, r = lin >> 4;
        *reinterpret_cast<float4*>(&qs[r * TS + d4 * 4]) =
            *reinterpret_cast<const float4*>(&Qb[(q0 + r) * DK + d4 * 4]);
    }

    uint64_t o2[8][2];
    float m[8], l[8];
#pragma unroll
    for (int i = 0; i < 8; i++) {
        o2[i][0] = 0ull; o2[i][1] = 0ull;
        m[i] = -1e30f; l[i] = 0.0f;
    }

    for (int t = t0; t < t1; t++) {
        const int k0 = t * 64;
        __syncthreads();   // all GEMM2 readers done -> ks/ps/vs free

        // K tile: ks[d][key] straight from g_Kt; V tile: vs[s][d]
#pragma unroll
        for (int i = 0; i < 8; i++) {
            int lin = tid + i * 128;
            int c4 = lin & 15, rr = lin >> 4;
            *reinterpret_cast<float4*>(&ks[rr * TS + c4 * 4]) =
                *reinterpret_cast<const float4*>(&Ktb[rr * S_ + k0 + c4 * 4]);
            *reinterpret_cast<float4*>(&vs[rr * TS + c4 * 4]) =
                *reinterpret_cast<const float4*>(&Vb[(k0 + rr) * DK + c4 * 4]);
        }
        __syncthreads();

        // GEMM1: S = Q @ K^T (contract over d). 8 rows/thread; halves of 4
        // rows to bound register staging.
        uint64_t s2[8][2];
#pragma unroll
        for (int i = 0; i < 8; i++) { s2[i][0] = 0ull; s2[i][1] = 0ull; }
#pragma unroll
        for (int d0 = 0; d0 < 64; d0 += 4) {
#pragma unroll
            for (int h = 0; h < 2; h++) {
                float4 qv[4];
#pragma unroll
                for (int i = 0; i < 4; i++)
                    qv[i] = *reinterpret_cast<const float4*>(&qs[(ty * 8 + h * 4 + i) * TS + d0]);
#pragma unroll
                for (int sub = 0; sub < 4; sub++) {
                    ulonglong2 kk = *reinterpret_cast<const ulonglong2*>(&ks[(d0 + sub) * TS + tx * 4]);
#pragma unroll
                    for (int i = 0; i < 4; i++) {
                        float q = (&qv[i].x)[sub];
                        uint64_t a = f2u(q, q);
                        fma2(s2[h * 4 + i][0], a, kk.x); fma2(s2[h * 4 + i][1], a, kk.y);
                    }
                }
            }
        }

        __syncthreads();   // ks fully consumed by ALL warps -> ps may overlay it

        // Online softmax update (masking only at the global diagonal tile)
        const bool maskt = (t == nkv - 1);
#pragma unroll
        for (int i = 0; i < 8; i++) {
            float pp[4];
            float2 a = u2f(s2[i][0]);
            float2 c = u2f(s2[i][1]);
            pp[0] = a.x; pp[1] = a.y; pp[2] = c.x; pp[3] = c.y;
            if (maskt) {
                int qrow = q0 + ty * 8 + i;
#pragma unroll
                for (int jn = 0; jn < 4; jn++)
                    if (k0 + tx * 4 + jn > qrow) pp[jn] = -1e30f;
            }
            float mi = fmaxf(fmaxf(pp[0], pp[1]), fmaxf(pp[2], pp[3]));
#pragma unroll
            for (int off = 8; off > 0; off >>= 1)
                mi = fmaxf(mi, __shfl_xor_sync(0xffffffffu, mi, off));
            float mnew = fmaxf(m[i], mi);
            float alpha = __expf(m[i] - mnew);
            float rs = 0.0f;
#pragma unroll
            for (int jn = 0; jn < 4; jn++) {
                float p = __expf(pp[jn] - mnew);
                pp[jn] = p;
                rs += p;
            }
#pragma unroll
            for (int off = 8; off > 0; off >>= 1)
                rs += __shfl_xor_sync(0xffffffffu, rs, off);
            l[i] = l[i] * alpha + rs;
            m[i] = mnew;
            uint64_t a2 = f2u(alpha, alpha);
            mul2(o2[i][0], a2); mul2(o2[i][1], a2);
            // P store (row-major, conflict-free); same-warp produce/consume
            *reinterpret_cast<float4*>(&ps[(ty * 8 + i) * TS + tx * 4]) =
                make_float4(pp[0], pp[1], pp[2], pp[3]);
        }
        __syncwarp();

        // GEMM2: O += P @ V (contract over s). Halves of 4 rows.
#pragma unroll
        for (int s0 = 0; s0 < 64; s0 += 4) {
#pragma unroll
            for (int h = 0; h < 2; h++) {
                float4 pv[4];
#pragma unroll
                for (int i = 0; i < 4; i++)
                    pv[i] = *reinterpret_cast<const float4*>(&ps[(ty * 8 + h * 4 + i) * TS + s0]);
#pragma unroll
                for (int sub = 0; sub < 4; sub++) {
                    ulonglong2 vv = *reinterpret_cast<const ulonglong2*>(&vs[(s0 + sub) * TS + tx * 4]);
#pragma unroll
                    for (int i = 0; i < 4; i++) {
                        float p = (&pv[i].x)[sub];
                        uint64_t a = f2u(p, p);
                        fma2(o2[h * 4 + i][0], a, vv.x); fma2(o2[h * 4 + i][1], a, vv.y);
                    }
                }
            }
        }
    }

    // Epilogue: write UNNORMALIZED partial O + (m, l)
    const int base = ((b * NS + split) * NJ + j) * 64;
#pragma unroll
    for (int i = 0; i < 8; i++) {
        const int r = ty * 8 + i;
        ulonglong2 o; o.x = o2[i][0]; o.y = o2[i][1];
        *reinterpret_cast<ulonglong2*>(&g_Opart[(base + r) * DK + tx * 4]) = o;
        if (tx == 0) g_ml[base + r] = make_float2(m[i], l[i]);
    }
}

// =====================================================================
// Kernel 3: combine partials. grid = (NJ, 4), block = 256.
// Thread handles one row-quarter: r = tid>>2 (0..63), 16 cols.
// =====================================================================
__global__ __launch_bounds__(256) void combine_kernel(float* __restrict__ out)
{
    const int j = blockIdx.x, b = blockIdx.y;
    const int tid = threadIdx.x;
    const int r = tid >> 2;
    const int c0 = (tid & 3) * 16;
    const int nkv = j + 1;
    const int per = (nkv + NS - 1) / NS;
    const int nsp = (nkv + per - 1) / per;   // non-empty splits

    float mv[NS], lv[NS];
    float M = -1e30f;
    for (int s = 0; s < nsp; s++) {
        float2 ml = g_ml[((b * NS + s) * NJ + j) * 64 + r];
        mv[s] = ml.x; lv[s] = ml.y;
        M = fmaxf(M, mv[s]);
    }
    float L = 0.0f, w[NS];
    for (int s = 0; s < nsp; s++) {
        w[s] = __expf(mv[s] - M);
        L += w[s] * lv[s];
    }
    const float inv = 1.0f / L;

    float4 acc[4];
#pragma unroll
    for (int q = 0; q < 4; q++) acc[q] = make_float4(0.f, 0.f, 0.f, 0.f);

    for (int s = 0; s < nsp; s++) {
        const float* Op = &g_Opart[(((b * NS + s) * NJ + j) * 64 + r) * DK + c0];
        const float ws = w[s];
#pragma unroll
        for (int q = 0; q < 4; q++) {
            float4 v = *reinterpret_cast<const float4*>(Op + q * 4);
            acc[q].x += ws * v.x; acc[q].y += ws * v.y;
            acc[q].z += ws * v.z; acc[q].w += ws * v.w;
        }
    }

    float* op = &out[((b * S_) + j * 64 + r) * DK + c0];
#pragma unroll
    for (int q = 0; q < 4; q++) {
        float4 v = make_float4(acc[q].x * inv, acc[q].y * inv,
                               acc[q].z * inv, acc[q].w * inv);
        *reinterpret_cast<float4*>(op + q * 4) = v;
    }
}

// =====================================================================
extern "C" void kernel_launch(void* const* d_in, const int* in_sizes, int n_in,
                              void* d_out, int out_size)
{
    const float* x  = (const float*)d_in[0];
    const float* WQ = (const float*)d_in[1];
    const float* WK = (const float*)d_in[2];
    const float* WV = (const float*)d_in[3];
    float* out = (float*)d_out;

    (void)in_sizes; (void)n_in; (void)out_size;

    cudaFuncSetAttribute(attn_kernel, cudaFuncAttributeMaxDynamicSharedMemorySize, SMEM_TOTAL);

    proj_kernel<<<256, 256>>>(x, WQ, WK, WV);
    attn_kernel<<<dim3(NJ, 4, NS), 128, SMEM_TOTAL>>>();
    combine_kernel<<<dim3(NJ, 4), 256>>>(out);
}